// round 16
// baseline (speedup 1.0000x reference)
#include <cuda_runtime.h>
#include <math.h>

#define SEQT 2048
#define INSZ 512
#define HID  1024
#define G4   4096   // 4*HID
#define OUTD 4

// ---------------- scratch (static device allocations only) ----------------
__device__ float g_gx[SEQT * G4];     // 32 MB: input projections + biases
__device__ float g_ys[SEQT * HID];    // 8 MB: LSTM outputs
__device__ float g_h1[SEQT * HID];    // 8 MB
__device__ float g_h2[SEQT * HID];    // 8 MB
__device__ float g_hbuf[2][HID];      // double-buffered recurrent state
__device__ unsigned g_arrive;         // monotonic arrival counter (reset each launch)

// ---------------- tiled SGEMM: C[M,N] = A[M,K] @ B[N,K]^T + bias (+bias2), opt ReLU
__global__ void __launch_bounds__(256) sgemm_bt(
    const float* __restrict__ A, const float* __restrict__ B,
    const float* __restrict__ bias, const float* __restrict__ bias2,
    float* __restrict__ C, int M, int N, int K, int relu)
{
    __shared__ float As[16][64];
    __shared__ float Bs[16][64];
    int tid = threadIdx.x;
    int tx = tid & 15, ty = tid >> 4;
    int m0 = blockIdx.y * 64, n0 = blockIdx.x * 64;

    int lm  = tid >> 2;
    int lk4 = tid & 3;

    const float4* Ag = (const float4*)(A + (size_t)(m0 + lm) * K) + lk4;
    const float4* Bg = (const float4*)(B + (size_t)(n0 + lm) * K) + lk4;

    float acc[4][4] = {};

    for (int k0 = 0; k0 < K; k0 += 16) {
        float4 av = *Ag; Ag += 4;
        float4 bv = *Bg; Bg += 4;
        __syncthreads();
        As[lk4 * 4 + 0][lm] = av.x; As[lk4 * 4 + 1][lm] = av.y;
        As[lk4 * 4 + 2][lm] = av.z; As[lk4 * 4 + 3][lm] = av.w;
        Bs[lk4 * 4 + 0][lm] = bv.x; Bs[lk4 * 4 + 1][lm] = bv.y;
        Bs[lk4 * 4 + 2][lm] = bv.z; Bs[lk4 * 4 + 3][lm] = bv.w;
        __syncthreads();
        #pragma unroll
        for (int k = 0; k < 16; k++) {
            float4 a4 = *(const float4*)&As[k][ty * 4];
            float4 b4 = *(const float4*)&Bs[k][tx * 4];
            float a_[4] = {a4.x, a4.y, a4.z, a4.w};
            float b_[4] = {b4.x, b4.y, b4.z, b4.w};
            #pragma unroll
            for (int i = 0; i < 4; i++)
                #pragma unroll
                for (int j = 0; j < 4; j++)
                    acc[i][j] = fmaf(a_[i], b_[j], acc[i][j]);
        }
    }

    int n = n0 + tx * 4;
    float bb[4];
    #pragma unroll
    for (int j = 0; j < 4; j++) {
        bb[j] = bias ? bias[n + j] : 0.f;
        if (bias2) bb[j] += bias2[n + j];
    }
    #pragma unroll
    for (int i = 0; i < 4; i++) {
        int m = m0 + ty * 4 + i;
        float4 r;
        r.x = acc[i][0] + bb[0];
        r.y = acc[i][1] + bb[1];
        r.z = acc[i][2] + bb[2];
        r.w = acc[i][3] + bb[3];
        if (relu) {
            r.x = fmaxf(r.x, 0.f); r.y = fmaxf(r.y, 0.f);
            r.z = fmaxf(r.z, 0.f); r.w = fmaxf(r.w, 0.f);
        }
        *(float4*)&C[(size_t)m * N + n] = r;
    }
}

// ---------------- sync helpers ----------------
__device__ __forceinline__ unsigned ld_relaxed_gpu(const unsigned* p)
{
    unsigned v;
    asm volatile("ld.relaxed.gpu.global.u32 %0, [%1];" : "=r"(v) : "l"(p) : "memory");
    return v;
}

// Depth-3 software-pipelined wait on a MONOTONIC counter: keeps 3 independent
// loads in flight so the sampling period is ~RT/3 instead of a full L2 round
// trip. Stale snapshots are conservative (counter only grows). Acquire fence
// after detect orders the subsequent h loads against producers' releases.
__device__ __forceinline__ void wait_counter(const unsigned* p, unsigned target)
{
    unsigned a = ld_relaxed_gpu(p);
    unsigned b = ld_relaxed_gpu(p);
    unsigned c = ld_relaxed_gpu(p);
    while ((int)(a - target) < 0) {
        a = b; b = c; c = ld_relaxed_gpu(p);
    }
    asm volatile("fence.acquire.gpu;" ::: "memory");
}

__device__ __forceinline__ void red_release_add(unsigned* p, unsigned v)
{
    asm volatile("red.release.gpu.global.add.u32 [%0], %1;" :: "l"(p), "r"(v) : "memory");
}

__device__ __forceinline__ float tanh_approx(float x)
{
    float r;
    asm("tanh.approx.f32 %0, %1;" : "=f"(r) : "f"(x));
    return r;
}

__device__ __forceinline__ float sigmoidf_(float x) { return 1.f / (1.f + __expf(-x)); }

__global__ void reset_kernel() { g_arrive = 0u; }

// ---------------- persistent LSTM recurrence ----------------
// grid = 128 blocks x 256 threads (8 warps), 1 block/SM. Warp w of block b owns
// hidden unit hu = 8b + w, computing all 4 gate rows.
// Weights register-resident (128 floats/lane, loaded once). Per step:
//   gx prefetch -> per-WARP pipelined poll -> warp stages its 128B h slice
//   -> syncthreads -> register FFMA + butterfly reduce -> activations
//   -> lane0 stores h -> syncthreads -> block arrive (red.release).
#define LSTM_BLOCKS 128
__global__ void __launch_bounds__(256, 1) lstm_kernel(
    const float* __restrict__ gx, const float* __restrict__ w_hh,
    const float* __restrict__ h0, const float* __restrict__ c0,
    float* __restrict__ ys, float* __restrict__ out)
{
    __shared__ float sh[HID];
    int tid  = threadIdx.x;
    int warp = tid >> 5, lane = tid & 31;
    int hu   = blockIdx.x * 8 + warp;          // 0..1023

    // hoist weights into registers: wrX[i] = w_hh[X*HID+hu][(lane+32i)*4 ..]
    float4 wr0[8], wr1[8], wr2[8], wr3[8];
    {
        const float4* p0 = (const float4*)(w_hh + (size_t)(0 * HID + hu) * HID) + lane;
        const float4* p1 = (const float4*)(w_hh + (size_t)(1 * HID + hu) * HID) + lane;
        const float4* p2 = (const float4*)(w_hh + (size_t)(2 * HID + hu) * HID) + lane;
        const float4* p3 = (const float4*)(w_hh + (size_t)(3 * HID + hu) * HID) + lane;
        #pragma unroll
        for (int i = 0; i < 8; i++) {
            wr0[i] = p0[i << 5];
            wr1[i] = p1[i << 5];
            wr2[i] = p2[i << 5];
            wr3[i] = p3[i << 5];
        }
    }
    const float* gxp = gx + (size_t)(lane & 3) * HID + hu;   // lanes 0..3: i,f,g,o

    float c = c0[hu];
    float hlast = h0[hu];
    if (lane == 0) __stcg(&g_hbuf[0][hu], hlast);
    __syncthreads();
    if (tid == 0) red_release_add(&g_arrive, 1u);

    for (int t = 0; t < SEQT; t++) {
        const float4* hb  = (const float4*)g_hbuf[t & 1];
        float*        hbn = g_hbuf[(t & 1) ^ 1];

        // prefetch this step's gx gate values (independent of other blocks)
        float gxv = 0.f;
        if (lane < 4) gxv = __ldcs(gxp + (size_t)t * G4);

        // per-warp pipelined poll, then the warp stages its own 128B slice
        unsigned target = (unsigned)(LSTM_BLOCKS * (t + 1));
        if (lane == 0) wait_counter(&g_arrive, target);
        __syncwarp();
        ((float4*)sh)[tid] = __ldcg(hb + tid);   // warp w covers float4 [32w, 32w+32)
        __syncthreads();

        // dot products: lane l covers float4 indices {l+32i}; weights in regs
        const float4* h4 = (const float4*)sh;
        float a0 = 0.f, a1 = 0.f, a2 = 0.f, a3 = 0.f;
        #pragma unroll
        for (int i = 0; i < 8; i++) {
            float4 x = h4[lane + (i << 5)];
            a0 = fmaf(wr0[i].x, x.x, a0); a0 = fmaf(wr0[i].y, x.y, a0);
            a0 = fmaf(wr0[i].z, x.z, a0); a0 = fmaf(wr0[i].w, x.w, a0);
            a1 = fmaf(wr1[i].x, x.x, a1); a1 = fmaf(wr1[i].y, x.y, a1);
            a1 = fmaf(wr1[i].z, x.z, a1); a1 = fmaf(wr1[i].w, x.w, a1);
            a2 = fmaf(wr2[i].x, x.x, a2); a2 = fmaf(wr2[i].y, x.y, a2);
            a2 = fmaf(wr2[i].z, x.z, a2); a2 = fmaf(wr2[i].w, x.w, a2);
            a3 = fmaf(wr3[i].x, x.x, a3); a3 = fmaf(wr3[i].y, x.y, a3);
            a3 = fmaf(wr3[i].z, x.z, a3); a3 = fmaf(wr3[i].w, x.w, a3);
        }

        // butterfly reductions: ALL lanes end with the 4 full sums
        #pragma unroll
        for (int off = 16; off; off >>= 1) {
            a0 += __shfl_xor_sync(0xffffffffu, a0, off);
            a1 += __shfl_xor_sync(0xffffffffu, a1, off);
            a2 += __shfl_xor_sync(0xffffffffu, a2, off);
            a3 += __shfl_xor_sync(0xffffffffu, a3, off);
        }

        // activations in parallel on lanes 0..3 (lane l owns gate l)
        float pre = ((lane == 0) ? a0 : (lane == 1) ? a1 : (lane == 2) ? a2 : a3) + gxv;
        float act = 0.f;
        if (lane < 4) act = (lane == 2) ? tanh_approx(pre) : sigmoidf_(pre);
        float i_ = __shfl_sync(0xffffffffu, act, 0);
        float f_ = __shfl_sync(0xffffffffu, act, 1);
        float g_ = __shfl_sync(0xffffffffu, act, 2);
        float o_ = __shfl_sync(0xffffffffu, act, 3);

        if (lane == 0) {
            c = fmaf(f_, c, i_ * g_);
            float h = o_ * tanh_approx(c);
            hlast = h;
            __stcg(&hbn[hu], h);
            __stcs(&ys[(size_t)t * HID + hu], h);
        }
        __syncthreads();                      // all 8 h writes of this block done
        if (tid == 0) red_release_add(&g_arrive, 1u);
    }

    // hT at out[16384..17407], cT at out[17408..18431]
    if (lane == 0) {
        out[2 * SEQT * OUTD + hu] = hlast;
        out[2 * SEQT * OUTD + HID + hu] = c;
    }
}

// ---------------- policy head ----------------
__global__ void __launch_bounds__(128) head_kernel(
    const float* __restrict__ h2, const float* __restrict__ mean_w,
    const float* __restrict__ mean_b, const float* __restrict__ log_std,
    float* __restrict__ out)
{
    __shared__ float sh[HID];
    int t = blockIdx.x;
    for (int i = threadIdx.x; i < HID; i += 128) sh[i] = h2[(size_t)t * HID + i];
    __syncthreads();
    int w = threadIdx.x >> 5, lane = threadIdx.x & 31;
    const float* wr = mean_w + (size_t)w * HID;
    float acc = 0.f;
    for (int k = lane; k < HID; k += 32) acc = fmaf(wr[k], sh[k], acc);
    #pragma unroll
    for (int o = 16; o; o >>= 1) acc += __shfl_down_sync(0xffffffffu, acc, o);
    if (lane == 0) {
        out[(size_t)t * OUTD + w] = acc + mean_b[w];
        out[SEQT * OUTD + (size_t)t * OUTD + w] = log_std[w];
    }
}

// ---------------- launcher ----------------
extern "C" void kernel_launch(void* const* d_in, const int* in_sizes, int n_in,
                              void* d_out, int out_size)
{
    const float* x      = (const float*)d_in[0];
    const float* h0     = (const float*)d_in[1];
    const float* c0     = (const float*)d_in[2];
    const float* w_ih   = (const float*)d_in[3];
    const float* w_hh   = (const float*)d_in[4];
    const float* b_ih   = (const float*)d_in[5];
    const float* b_hh   = (const float*)d_in[6];
    const float* fc1_w  = (const float*)d_in[7];
    const float* fc1_b  = (const float*)d_in[8];
    const float* fc2_w  = (const float*)d_in[9];
    const float* fc2_b  = (const float*)d_in[10];
    const float* mean_w = (const float*)d_in[11];
    const float* mean_b = (const float*)d_in[12];
    const float* lstd   = (const float*)d_in[13];
    float* out = (float*)d_out;

    float *gx, *ys, *h1, *h2;
    cudaGetSymbolAddress((void**)&gx, g_gx);
    cudaGetSymbolAddress((void**)&ys, g_ys);
    cudaGetSymbolAddress((void**)&h1, g_h1);
    cudaGetSymbolAddress((void**)&h2, g_h2);

    // gx = x @ w_ih^T + b_ih + b_hh : [2048, 4096]
    sgemm_bt<<<dim3(G4 / 64, SEQT / 64), 256>>>(x, w_ih, b_ih, b_hh, gx,
                                                SEQT, G4, INSZ, 0);
    // reset arrival counter (same stream: ordered, graph-capturable)
    reset_kernel<<<1, 1>>>();
    // recurrence (persistent; also writes hT, cT into out)
    lstm_kernel<<<LSTM_BLOCKS, 256>>>(gx, w_hh, h0, c0, ys, out);
    // fc1, fc2 with ReLU
    sgemm_bt<<<dim3(HID / 64, SEQT / 64), 256>>>(ys, fc1_w, fc1_b, nullptr, h1,
                                                 SEQT, HID, HID, 1);
    sgemm_bt<<<dim3(HID / 64, SEQT / 64), 256>>>(h1, fc2_w, fc2_b, nullptr, h2,
                                                 SEQT, HID, HID, 1);
    // head: action_mean + action_log_std
    head_kernel<<<SEQT, 128>>>(h2, mean_w, mean_b, lstd, out);
}

// round 17
// speedup vs baseline: 1.2425x; 1.2425x over previous
#include <cuda_runtime.h>
#include <math.h>

#define SEQT 2048
#define INSZ 512
#define HID  1024
#define G4   4096   // 4*HID
#define OUTD 4

// ---------------- scratch (static device allocations only) ----------------
__device__ float g_gx[SEQT * G4];     // 32 MB: input projections + biases
__device__ float g_ys[SEQT * HID];    // 8 MB: LSTM outputs
__device__ float g_h1[SEQT * HID];    // 8 MB
__device__ float g_h2[SEQT * HID];    // 8 MB
__device__ float g_hbuf[2][HID];      // double-buffered recurrent state
__device__ unsigned g_arrive;         // monotonic arrival counter (reset each launch)

// ---------------- tiled SGEMM: C[M,N] = A[M,K] @ B[N,K]^T + bias (+bias2), opt ReLU
__global__ void __launch_bounds__(256) sgemm_bt(
    const float* __restrict__ A, const float* __restrict__ B,
    const float* __restrict__ bias, const float* __restrict__ bias2,
    float* __restrict__ C, int M, int N, int K, int relu)
{
    __shared__ float As[16][64];
    __shared__ float Bs[16][64];
    int tid = threadIdx.x;
    int tx = tid & 15, ty = tid >> 4;
    int m0 = blockIdx.y * 64, n0 = blockIdx.x * 64;

    int lm  = tid >> 2;
    int lk4 = tid & 3;

    const float4* Ag = (const float4*)(A + (size_t)(m0 + lm) * K) + lk4;
    const float4* Bg = (const float4*)(B + (size_t)(n0 + lm) * K) + lk4;

    float acc[4][4] = {};

    for (int k0 = 0; k0 < K; k0 += 16) {
        float4 av = *Ag; Ag += 4;
        float4 bv = *Bg; Bg += 4;
        __syncthreads();
        As[lk4 * 4 + 0][lm] = av.x; As[lk4 * 4 + 1][lm] = av.y;
        As[lk4 * 4 + 2][lm] = av.z; As[lk4 * 4 + 3][lm] = av.w;
        Bs[lk4 * 4 + 0][lm] = bv.x; Bs[lk4 * 4 + 1][lm] = bv.y;
        Bs[lk4 * 4 + 2][lm] = bv.z; Bs[lk4 * 4 + 3][lm] = bv.w;
        __syncthreads();
        #pragma unroll
        for (int k = 0; k < 16; k++) {
            float4 a4 = *(const float4*)&As[k][ty * 4];
            float4 b4 = *(const float4*)&Bs[k][tx * 4];
            float a_[4] = {a4.x, a4.y, a4.z, a4.w};
            float b_[4] = {b4.x, b4.y, b4.z, b4.w};
            #pragma unroll
            for (int i = 0; i < 4; i++)
                #pragma unroll
                for (int j = 0; j < 4; j++)
                    acc[i][j] = fmaf(a_[i], b_[j], acc[i][j]);
        }
    }

    int n = n0 + tx * 4;
    float bb[4];
    #pragma unroll
    for (int j = 0; j < 4; j++) {
        bb[j] = bias ? bias[n + j] : 0.f;
        if (bias2) bb[j] += bias2[n + j];
    }
    #pragma unroll
    for (int i = 0; i < 4; i++) {
        int m = m0 + ty * 4 + i;
        float4 r;
        r.x = acc[i][0] + bb[0];
        r.y = acc[i][1] + bb[1];
        r.z = acc[i][2] + bb[2];
        r.w = acc[i][3] + bb[3];
        if (relu) {
            r.x = fmaxf(r.x, 0.f); r.y = fmaxf(r.y, 0.f);
            r.z = fmaxf(r.z, 0.f); r.w = fmaxf(r.w, 0.f);
        }
        *(float4*)&C[(size_t)m * N + n] = r;
    }
}

// ---------------- sync helpers ----------------
__device__ __forceinline__ unsigned ld_relaxed_gpu(const unsigned* p)
{
    unsigned v;
    asm volatile("ld.relaxed.gpu.global.u32 %0, [%1];" : "=r"(v) : "l"(p) : "memory");
    return v;
}

// Depth-3 software-pipelined wait on a MONOTONIC counter. Used by exactly ONE
// thread per block (128 chip-wide): keeps 3 independent loads in flight so the
// sampling period is ~RT/3 instead of a full L2 round trip. Stale snapshots are
// conservative (counter only grows). Acquire fence after detect orders the
// subsequent h loads against producers' releases.
__device__ __forceinline__ void wait_counter(const unsigned* p, unsigned target)
{
    unsigned a = ld_relaxed_gpu(p);
    unsigned b = ld_relaxed_gpu(p);
    unsigned c = ld_relaxed_gpu(p);
    while ((int)(a - target) < 0) {
        a = b; b = c; c = ld_relaxed_gpu(p);
    }
    asm volatile("fence.acquire.gpu;" ::: "memory");
}

__device__ __forceinline__ void red_release_add(unsigned* p, unsigned v)
{
    asm volatile("red.release.gpu.global.add.u32 [%0], %1;" :: "l"(p), "r"(v) : "memory");
}

__device__ __forceinline__ float tanh_approx(float x)
{
    float r;
    asm("tanh.approx.f32 %0, %1;" : "=f"(r) : "f"(x));
    return r;
}

__device__ __forceinline__ float sigmoidf_(float x) { return 1.f / (1.f + __expf(-x)); }

__global__ void reset_kernel() { g_arrive = 0u; }

// ---------------- persistent LSTM recurrence ----------------
// grid = 128 blocks x 256 threads (8 warps), 1 block/SM. Warp w of block b owns
// hidden unit hu = 8b + w, computing all 4 gate rows.
// Weights register-resident (128 floats/lane, loaded once). Sync = R13 scheme
// (best measured): single global counter, red.release arrive per block, ONE
// poller thread per block — now with depth-3 pipelined sampling.
#define LSTM_BLOCKS 128
__global__ void __launch_bounds__(256, 1) lstm_kernel(
    const float* __restrict__ gx, const float* __restrict__ w_hh,
    const float* __restrict__ h0, const float* __restrict__ c0,
    float* __restrict__ ys, float* __restrict__ out)
{
    __shared__ float sh[HID];
    int tid  = threadIdx.x;
    int warp = tid >> 5, lane = tid & 31;
    int hu   = blockIdx.x * 8 + warp;          // 0..1023

    // hoist weights into registers: wrX[i] = w_hh[X*HID+hu][(lane+32i)*4 ..]
    float4 wr0[8], wr1[8], wr2[8], wr3[8];
    {
        const float4* p0 = (const float4*)(w_hh + (size_t)(0 * HID + hu) * HID) + lane;
        const float4* p1 = (const float4*)(w_hh + (size_t)(1 * HID + hu) * HID) + lane;
        const float4* p2 = (const float4*)(w_hh + (size_t)(2 * HID + hu) * HID) + lane;
        const float4* p3 = (const float4*)(w_hh + (size_t)(3 * HID + hu) * HID) + lane;
        #pragma unroll
        for (int i = 0; i < 8; i++) {
            wr0[i] = p0[i << 5];
            wr1[i] = p1[i << 5];
            wr2[i] = p2[i << 5];
            wr3[i] = p3[i << 5];
        }
    }
    const float* gxp = gx + (size_t)(lane & 3) * HID + hu;   // lanes 0..3: i,f,g,o

    float c = c0[hu];
    float hlast = h0[hu];
    if (lane == 0) __stcg(&g_hbuf[0][hu], hlast);
    __syncthreads();
    if (tid == 0) red_release_add(&g_arrive, 1u);

    for (int t = 0; t < SEQT; t++) {
        const float4* hb  = (const float4*)g_hbuf[t & 1];
        float*        hbn = g_hbuf[(t & 1) ^ 1];

        // prefetch this step's gx gate values (independent of other blocks)
        float gxv = 0.f;
        if (lane < 4) gxv = __ldcs(gxp + (size_t)t * G4);

        // single poller per block, pipelined sampling of the counter line
        if (tid == 0) {
            unsigned target = (unsigned)(LSTM_BLOCKS * (t + 1));
            wait_counter(&g_arrive, target);
        }
        __syncthreads();

        // stage h(t) into shared: 256 threads x float4 = 4KB in one round
        ((float4*)sh)[tid] = __ldcg(hb + tid);
        __syncthreads();

        // dot products: lane l covers float4 indices {l+32i}; weights in regs
        const float4* h4 = (const float4*)sh;
        float a0 = 0.f, a1 = 0.f, a2 = 0.f, a3 = 0.f;
        #pragma unroll
        for (int i = 0; i < 8; i++) {
            float4 x = h4[lane + (i << 5)];
            a0 = fmaf(wr0[i].x, x.x, a0); a0 = fmaf(wr0[i].y, x.y, a0);
            a0 = fmaf(wr0[i].z, x.z, a0); a0 = fmaf(wr0[i].w, x.w, a0);
            a1 = fmaf(wr1[i].x, x.x, a1); a1 = fmaf(wr1[i].y, x.y, a1);
            a1 = fmaf(wr1[i].z, x.z, a1); a1 = fmaf(wr1[i].w, x.w, a1);
            a2 = fmaf(wr2[i].x, x.x, a2); a2 = fmaf(wr2[i].y, x.y, a2);
            a2 = fmaf(wr2[i].z, x.z, a2); a2 = fmaf(wr2[i].w, x.w, a2);
            a3 = fmaf(wr3[i].x, x.x, a3); a3 = fmaf(wr3[i].y, x.y, a3);
            a3 = fmaf(wr3[i].z, x.z, a3); a3 = fmaf(wr3[i].w, x.w, a3);
        }

        // butterfly reductions: ALL lanes end with the 4 full sums
        #pragma unroll
        for (int off = 16; off; off >>= 1) {
            a0 += __shfl_xor_sync(0xffffffffu, a0, off);
            a1 += __shfl_xor_sync(0xffffffffu, a1, off);
            a2 += __shfl_xor_sync(0xffffffffu, a2, off);
            a3 += __shfl_xor_sync(0xffffffffu, a3, off);
        }

        // activations in parallel on lanes 0..3 (lane l owns gate l)
        float pre = ((lane == 0) ? a0 : (lane == 1) ? a1 : (lane == 2) ? a2 : a3) + gxv;
        float act = 0.f;
        if (lane < 4) act = (lane == 2) ? tanh_approx(pre) : sigmoidf_(pre);
        float i_ = __shfl_sync(0xffffffffu, act, 0);
        float f_ = __shfl_sync(0xffffffffu, act, 1);
        float g_ = __shfl_sync(0xffffffffu, act, 2);
        float o_ = __shfl_sync(0xffffffffu, act, 3);

        if (lane == 0) {
            c = fmaf(f_, c, i_ * g_);
            float h = o_ * tanh_approx(c);
            hlast = h;
            __stcg(&hbn[hu], h);
            __stcs(&ys[(size_t)t * HID + hu], h);
        }
        __syncthreads();                      // all 8 h writes of this block done
        if (tid == 0) red_release_add(&g_arrive, 1u);
    }

    // hT at out[16384..17407], cT at out[17408..18431]
    if (lane == 0) {
        out[2 * SEQT * OUTD + hu] = hlast;
        out[2 * SEQT * OUTD + HID + hu] = c;
    }
}

// ---------------- policy head ----------------
__global__ void __launch_bounds__(128) head_kernel(
    const float* __restrict__ h2, const float* __restrict__ mean_w,
    const float* __restrict__ mean_b, const float* __restrict__ log_std,
    float* __restrict__ out)
{
    __shared__ float sh[HID];
    int t = blockIdx.x;
    for (int i = threadIdx.x; i < HID; i += 128) sh[i] = h2[(size_t)t * HID + i];
    __syncthreads();
    int w = threadIdx.x >> 5, lane = threadIdx.x & 31;
    const float* wr = mean_w + (size_t)w * HID;
    float acc = 0.f;
    for (int k = lane; k < HID; k += 32) acc = fmaf(wr[k], sh[k], acc);
    #pragma unroll
    for (int o = 16; o; o >>= 1) acc += __shfl_down_sync(0xffffffffu, acc, o);
    if (lane == 0) {
        out[(size_t)t * OUTD + w] = acc + mean_b[w];
        out[SEQT * OUTD + (size_t)t * OUTD + w] = log_std[w];
    }
}

// ---------------- launcher ----------------
extern "C" void kernel_launch(void* const* d_in, const int* in_sizes, int n_in,
                              void* d_out, int out_size)
{
    const float* x      = (const float*)d_in[0];
    const float* h0     = (const float*)d_in[1];
    const float* c0     = (const float*)d_in[2];
    const float* w_ih   = (const float*)d_in[3];
    const float* w_hh   = (const float*)d_in[4];
    const float* b_ih   = (const float*)d_in[5];
    const float* b_hh   = (const float*)d_in[6];
    const float* fc1_w  = (const float*)d_in[7];
    const float* fc1_b  = (const float*)d_in[8];
    const float* fc2_w  = (const float*)d_in[9];
    const float* fc2_b  = (const float*)d_in[10];
    const float* mean_w = (const float*)d_in[11];
    const float* mean_b = (const float*)d_in[12];
    const float* lstd   = (const float*)d_in[13];
    float* out = (float*)d_out;

    float *gx, *ys, *h1, *h2;
    cudaGetSymbolAddress((void**)&gx, g_gx);
    cudaGetSymbolAddress((void**)&ys, g_ys);
    cudaGetSymbolAddress((void**)&h1, g_h1);
    cudaGetSymbolAddress((void**)&h2, g_h2);

    // gx = x @ w_ih^T + b_ih + b_hh : [2048, 4096]
    sgemm_bt<<<dim3(G4 / 64, SEQT / 64), 256>>>(x, w_ih, b_ih, b_hh, gx,
                                                SEQT, G4, INSZ, 0);
    // reset arrival counter (same stream: ordered, graph-capturable)
    reset_kernel<<<1, 1>>>();
    // recurrence (persistent; also writes hT, cT into out)
    lstm_kernel<<<LSTM_BLOCKS, 256>>>(gx, w_hh, h0, c0, ys, out);
    // fc1, fc2 with ReLU
    sgemm_bt<<<dim3(HID / 64, SEQT / 64), 256>>>(ys, fc1_w, fc1_b, nullptr, h1,
                                                 SEQT, HID, HID, 1);
    sgemm_bt<<<dim3(HID / 64, SEQT / 64), 256>>>(h1, fc2_w, fc2_b, nullptr, h2,
                                                 SEQT, HID, HID, 1);
    // head: action_mean + action_log_std
    head_kernel<<<SEQT, 128>>>(h2, mean_w, mean_b, lstd, out);
}